// round 13
// baseline (speedup 1.0000x reference)
#include <cuda_runtime.h>
#include <cuda_bf16.h>
#include <cstdint>

#define D 512
#define NDRUGS 4096
#define CAP 128
#define MAXEDGES 262144
#define BM 64
#define BN 128
#define BK 64

// ---------------- device scratch (allocation-free) ----------------
__device__ __align__(16) __nv_bfloat16  g_Uh[NDRUGS * D];    // 4 MB
__device__ __align__(16) __nv_bfloat16  g_Ah[NDRUGS * D];    // 4 MB
__device__ __align__(16) __nv_bfloat16  g_Bh[D * D];         // 512 KB
__device__ int  g_cnt[NDRUGS];                               // zero-init; compact resets
__device__ int  g_total;                                     // zero-init; edge resets
__device__ __align__(16) int2 g_bkt[NDRUGS * CAP];           // 4 MB buckets
__device__ __align__(16) int4 g_flat[MAXEDGES];              // 4 MB row-sorted (r,c,e,_)

// ---------------- helpers ----------------
__device__ __forceinline__ uint32_t smem_to_u32(const void* p) {
    uint32_t a;
    asm("{ .reg .u64 t; cvta.to.shared.u64 t, %1; cvt.u32.u64 %0, t; }" : "=r"(a) : "l"(p));
    return a;
}
#define SMEM_SWIZZLE_128B(o) ((o) ^ (((o) >> 3) & 0x70))

#define CP_ASYNC16(dst, src) \
    asm volatile("cp.async.cg.shared.global [%0], [%1], 16;" :: "r"(dst), "l"(src))
#define CP_COMMIT() asm volatile("cp.async.commit_group;" ::: "memory")
#define CP_WAIT(n)  asm volatile("cp.async.wait_group %0;" :: "n"(n) : "memory")

__device__ __forceinline__ void ldsm_x4(uint32_t& r0, uint32_t& r1, uint32_t& r2, uint32_t& r3,
                                        uint32_t addr) {
    asm volatile("ldmatrix.sync.aligned.m8n8.x4.shared.b16 {%0,%1,%2,%3}, [%4];"
                 : "=r"(r0), "=r"(r1), "=r"(r2), "=r"(r3) : "r"(addr));
}
__device__ __forceinline__ void mma_bf16(float* c, const uint32_t* a, uint32_t b0, uint32_t b1) {
    asm volatile("mma.sync.aligned.m16n8k16.row.col.f32.bf16.bf16.f32 "
                 "{%0,%1,%2,%3}, {%4,%5,%6,%7}, {%8,%9}, {%0,%1,%2,%3};"
                 : "+f"(c[0]), "+f"(c[1]), "+f"(c[2]), "+f"(c[3])
                 : "r"(a[0]), "r"(a[1]), "r"(a[2]), "r"(a[3]), "r"(b0), "r"(b1));
}

// GEMM SMEM: 3 stages x (A 8K | B 16K) = 72 KB
#define STAGE_BYTES 24576
#define A_OFF 0
#define B_OFF 8192
#define SM_GEMM (3 * STAGE_BYTES)

// ---------------------------------------------------------------------------
// Prep A: Ah = bf16(z[m,k] * d[k])
// ---------------------------------------------------------------------------
__global__ __launch_bounds__(256) void prep_a_kernel(
    const float* __restrict__ z, const float* __restrict__ ldiag, const int* __restrict__ idxp)
{
    const float* dp = ldiag + idxp[0] * D;
    int i = blockIdx.x * 256 + threadIdx.x;
    int k4 = (i & (D / 4 - 1)) << 2;
    float4 v = ((const float4*)z)[i];
    v.x *= dp[k4 + 0]; v.y *= dp[k4 + 1]; v.z *= dp[k4 + 2]; v.w *= dp[k4 + 3];

    __nv_bfloat162 h01 = __floats2bfloat162_rn(v.x, v.y);
    __nv_bfloat162 h23 = __floats2bfloat162_rn(v.z, v.w);
    uint2 hp; hp.x = *(uint32_t*)&h01; hp.y = *(uint32_t*)&h23;
    ((uint2*)g_Ah)[i] = hp;
}

// ---------------------------------------------------------------------------
// Prep W: Bh[n,k] = bf16(W[k,n])
// ---------------------------------------------------------------------------
__global__ __launch_bounds__(256) void prep_w_kernel(const float* __restrict__ W)
{
    __shared__ float t[32][33];
    int tx = threadIdx.x, ty = threadIdx.y;
    int x0 = blockIdx.x * 32, y0 = blockIdx.y * 32;
    #pragma unroll
    for (int r = 0; r < 4; r++)
        t[ty + r * 8][tx] = W[(y0 + ty + r * 8) * D + x0 + tx];
    __syncthreads();
    #pragma unroll
    for (int r = 0; r < 4; r++) {
        int n = x0 + ty + r * 8;
        int k = y0 + tx;
        g_Bh[n * D + k] = __float2bfloat16(t[tx][ty + r * 8]);
    }
}

// ---------------------------------------------------------------------------
// Scatter: bucket edges by row index
// ---------------------------------------------------------------------------
__global__ __launch_bounds__(256) void scatter_kernel(const int* __restrict__ edges, int n_edges)
{
    int e = blockIdx.x * 256 + threadIdx.x;
    if (e < n_edges) {
        int r = edges[e];
        int c = edges[n_edges + e];
        int p = atomicAdd(&g_cnt[r], 1);
        if (p < CAP) g_bkt[r * CAP + p] = make_int2(c, e);
    }
}

// ---------------------------------------------------------------------------
// Compact: one warp per drug; reserve run via atomic cursor, copy bucket to
// the flat (r,c,e) array. Resets g_cnt for the next graph replay.
// ---------------------------------------------------------------------------
__global__ __launch_bounds__(256) void compact_kernel()
{
    int warp = (blockIdx.x * 256 + threadIdx.x) >> 5;
    int lane = threadIdx.x & 31;
    if (warp >= NDRUGS) return;

    int cnt = g_cnt[warp];
    if (cnt > CAP) cnt = CAP;
    int pos = 0;
    if (lane == 0 && cnt > 0) pos = atomicAdd(&g_total, cnt);
    pos = __shfl_sync(0xffffffffu, pos, 0);

    const int2* b = g_bkt + warp * CAP;
    for (int i = lane; i < cnt; i += 32) {
        int2 ce = b[i];
        g_flat[pos + i] = make_int4(warp, ce.x, ce.y, 0);
    }
    if (lane == 0) g_cnt[warp] = 0;
}

// ---------------------------------------------------------------------------
// bf16 GEMM via mma.sync: Uh = bf16( Ah @ Wh )   (R12 shape)
// ---------------------------------------------------------------------------
__global__ __launch_bounds__(256, 2) void dedicom_mma_kernel()
{
    extern __shared__ char smem[];
    const int tid  = threadIdx.x;
    const int wid  = tid >> 5;
    const int lane = tid & 31;
    const int m0 = blockIdx.y * BM;
    const int n0 = blockIdx.x * BN;
    const uint32_t sbase = smem_to_u32(smem);

    const int wm = (wid & 3) * 16;
    const int wn = (wid >> 2) * 64;

    float acc[8][4];
    #pragma unroll
    for (int b = 0; b < 8; b++)
        #pragma unroll
        for (int c = 0; c < 4; c++) acc[b][c] = 0.f;

    auto load_stage = [&](int kc, int stg) {
        const int k0 = kc * BK;
        const uint32_t sb = sbase + stg * STAGE_BYTES;
        #pragma unroll
        for (int t = tid; t < 512; t += 256) {
            int m = t >> 3, j = t & 7;
            uint32_t sw = SMEM_SWIZZLE_128B((uint32_t)(m * 128 + j * 16));
            CP_ASYNC16(sb + A_OFF + sw, (const char*)(g_Ah + (m0 + m) * D + k0) + j * 16);
        }
        #pragma unroll
        for (int t = tid; t < 1024; t += 256) {
            int n = t >> 3, j = t & 7;
            uint32_t sw = SMEM_SWIZZLE_128B((uint32_t)(n * 128 + j * 16));
            CP_ASYNC16(sb + B_OFF + sw, (const char*)(g_Bh + (n0 + n) * D + k0) + j * 16);
        }
    };

    const int NKC = D / BK;
    load_stage(0, 0); CP_COMMIT();
    load_stage(1, 1); CP_COMMIT();

    for (int kc = 0; kc < NKC; kc++) {
        CP_WAIT(1);
        __syncthreads();

        const uint32_t sb = sbase + (kc % 3) * STAGE_BYTES;

        #pragma unroll
        for (int ks = 0; ks < BK / 16; ks++) {
            uint32_t a[4], bh[4][4];
            {
                uint32_t off = SMEM_SWIZZLE_128B(
                    (uint32_t)((wm + (lane & 15)) * 128 + ks * 32 + (lane >> 4) * 16));
                ldsm_x4(a[0], a[1], a[2], a[3], sb + A_OFF + off);
            }
            #pragma unroll
            for (int p = 0; p < 4; p++) {
                uint32_t off = SMEM_SWIZZLE_128B(
                    (uint32_t)((wn + p * 16 + ((lane >> 4) * 8) + (lane & 7)) * 128
                               + ks * 32 + ((lane >> 3) & 1) * 16));
                ldsm_x4(bh[p][0], bh[p][1], bh[p][2], bh[p][3], sb + B_OFF + off);
            }
            #pragma unroll
            for (int p = 0; p < 4; p++) {
                mma_bf16(acc[2 * p + 0], a, bh[p][0], bh[p][1]);
                mma_bf16(acc[2 * p + 1], a, bh[p][2], bh[p][3]);
            }
        }

        if (kc + 2 < NKC) { load_stage(kc + 2, (kc + 2) % 3); CP_COMMIT(); }
    }

    const int g  = lane >> 2;
    const int c2 = (lane & 3) * 2;
    const int row0 = m0 + wm + g;
    #pragma unroll
    for (int nt = 0; nt < 8; nt++) {
        const int col = wn + nt * 8 + c2;
        __nv_bfloat162 v0 = __floats2bfloat162_rn(acc[nt][0], acc[nt][1]);
        __nv_bfloat162 v1 = __floats2bfloat162_rn(acc[nt][2], acc[nt][3]);
        *(__nv_bfloat162*)(g_Uh + (long)row0 * D + n0 + col)       = v0;
        *(__nv_bfloat162*)(g_Uh + (long)(row0 + 8) * D + n0 + col) = v1;
    }
}

// ---------------------------------------------------------------------------
// Phase 2: flat warp-per-edge body (proven), fed by the ROW-SORTED edge list.
// 8 warps of a CTA hit the same Uh row -> L1 dedup -> row LTS traffic /8.
// Resets g_total for the next graph replay.
// ---------------------------------------------------------------------------
__global__ __launch_bounds__(256) void dedicom_edge_kernel(
    float* __restrict__ out, int n_edges)
{
    if (blockIdx.x == 0 && threadIdx.x == 0) g_total = 0;

    const int w    = (blockIdx.x * blockDim.x + threadIdx.x) >> 5;
    const int lane = threadIdx.x & 31;
    if (w >= n_edges) return;

    const int4 rce = g_flat[w];          // same addr across warp -> broadcast

    const uint4* vr = (const uint4*)(g_Uh + (long)rce.x * D);
    const uint4* zc = (const uint4*)(g_Ah + (long)rce.y * D);

    __nv_bfloat162 z2 = __floats2bfloat162_rn(0.f, 0.f);
    __nv_bfloat162 q0 = z2, q1 = z2, q2 = z2, q3 = z2;

    #pragma unroll
    for (int i = 0; i < 2; i++) {
        uint4 a = __ldg(&vr[lane + i * 32]);
        uint4 b = __ldg(&zc[lane + i * 32]);
        q0 = __hfma2(*(const __nv_bfloat162*)&a.x, *(const __nv_bfloat162*)&b.x, q0);
        q1 = __hfma2(*(const __nv_bfloat162*)&a.y, *(const __nv_bfloat162*)&b.y, q1);
        q2 = __hfma2(*(const __nv_bfloat162*)&a.z, *(const __nv_bfloat162*)&b.z, q2);
        q3 = __hfma2(*(const __nv_bfloat162*)&a.w, *(const __nv_bfloat162*)&b.w, q3);
    }

    float2 f0 = __bfloat1622float2(q0);
    float2 f1 = __bfloat1622float2(q1);
    float2 f2 = __bfloat1622float2(q2);
    float2 f3 = __bfloat1622float2(q3);
    float acc = ((f0.x + f0.y) + (f1.x + f1.y)) + ((f2.x + f2.y) + (f3.x + f3.y));

    #pragma unroll
    for (int o = 16; o; o >>= 1) acc += __shfl_xor_sync(0xffffffffu, acc, o);

    if (lane == 0) out[rce.z] = 1.f / (1.f + __expf(-acc));
}

// ---------------------------------------------------------------------------
// Launch
// ---------------------------------------------------------------------------
extern "C" void kernel_launch(void* const* d_in, const int* in_sizes, int n_in,
                              void* d_out, int out_size)
{
    const float* z     = (const float*)d_in[0];   // [4096, 512]
    const float* W     = (const float*)d_in[1];   // [512, 512]
    const float* ldiag = (const float*)d_in[2];   // [10, 512]
    const int*   edges = (const int*)d_in[3];     // [2, n_edges] int32
    const int*   idxp  = (const int*)d_in[4];     // scalar

    const int n_drugs = in_sizes[0] / D;
    const int n_edges = in_sizes[3] / 2;

    static int smem_set = 0;
    if (!smem_set) {
        cudaFuncSetAttribute(dedicom_mma_kernel,
                             cudaFuncAttributeMaxDynamicSharedMemorySize, SM_GEMM);
        smem_set = 1;
    }

    prep_a_kernel<<<(n_drugs * D / 4 + 255) / 256, 256>>>(z, ldiag, idxp);
    prep_w_kernel<<<dim3(D / 32, D / 32), dim3(32, 8)>>>(W);
    scatter_kernel<<<(n_edges + 255) / 256, 256>>>(edges, n_edges);
    compact_kernel<<<(n_drugs / 8 + 0), 256>>>();   // 4096 warps

    dim3 gm(D / BN, n_drugs / BM);
    dedicom_mma_kernel<<<gm, 256, SM_GEMM>>>();

    int blocks = (n_edges + 7) / 8;
    dedicom_edge_kernel<<<blocks, 256>>>((float*)d_out, n_edges);
}

// round 14
// speedup vs baseline: 1.0437x; 1.0437x over previous
#include <cuda_runtime.h>
#include <cuda_bf16.h>
#include <cstdint>

#define D 512
#define NDRUGS 4096
#define MAXEDGES 262144
#define BM 64
#define BN 128
#define BK 64

// ---------------- device scratch (allocation-free) ----------------
__device__ __align__(16) __nv_bfloat16  g_Uh[NDRUGS * D];    // 4 MB (U = (z*d)@W)
__device__ __align__(16) __nv_bfloat16  g_Ah[NDRUGS * D];    // 4 MB (bf16 of z*d)
__device__ __align__(16) __nv_bfloat16  g_Bh[D * D];         // 512 KB (W^T bf16)
__device__ float g_part[2 * MAXEDGES];                       // 2 MB partial scores

// ---------------- helpers ----------------
__device__ __forceinline__ uint32_t smem_to_u32(const void* p) {
    uint32_t a;
    asm("{ .reg .u64 t; cvta.to.shared.u64 t, %1; cvt.u32.u64 %0, t; }" : "=r"(a) : "l"(p));
    return a;
}
#define SMEM_SWIZZLE_128B(o) ((o) ^ (((o) >> 3) & 0x70))

#define CP_ASYNC16(dst, src) \
    asm volatile("cp.async.cg.shared.global [%0], [%1], 16;" :: "r"(dst), "l"(src))
#define CP_COMMIT() asm volatile("cp.async.commit_group;" ::: "memory")
#define CP_WAIT(n)  asm volatile("cp.async.wait_group %0;" :: "n"(n) : "memory")

__device__ __forceinline__ void ldsm_x4(uint32_t& r0, uint32_t& r1, uint32_t& r2, uint32_t& r3,
                                        uint32_t addr) {
    asm volatile("ldmatrix.sync.aligned.m8n8.x4.shared.b16 {%0,%1,%2,%3}, [%4];"
                 : "=r"(r0), "=r"(r1), "=r"(r2), "=r"(r3) : "r"(addr));
}
__device__ __forceinline__ void mma_bf16(float* c, const uint32_t* a, uint32_t b0, uint32_t b1) {
    asm volatile("mma.sync.aligned.m16n8k16.row.col.f32.bf16.bf16.f32 "
                 "{%0,%1,%2,%3}, {%4,%5,%6,%7}, {%8,%9}, {%0,%1,%2,%3};"
                 : "+f"(c[0]), "+f"(c[1]), "+f"(c[2]), "+f"(c[3])
                 : "r"(a[0]), "r"(a[1]), "r"(a[2]), "r"(a[3]), "r"(b0), "r"(b1));
}

// GEMM SMEM: 3 stages x (A 8K | B 16K) = 72 KB
#define STAGE_BYTES 24576
#define A_OFF 0
#define B_OFF 8192
#define SM_GEMM (3 * STAGE_BYTES)

// ---------------------------------------------------------------------------
// Prep A: Ah = bf16(z[m,k] * d[k])
// ---------------------------------------------------------------------------
__global__ __launch_bounds__(256) void prep_a_kernel(
    const float* __restrict__ z, const float* __restrict__ ldiag, const int* __restrict__ idxp)
{
    const float* dp = ldiag + idxp[0] * D;
    int i = blockIdx.x * 256 + threadIdx.x;
    int k4 = (i & (D / 4 - 1)) << 2;
    float4 v = ((const float4*)z)[i];
    v.x *= dp[k4 + 0]; v.y *= dp[k4 + 1]; v.z *= dp[k4 + 2]; v.w *= dp[k4 + 3];

    __nv_bfloat162 h01 = __floats2bfloat162_rn(v.x, v.y);
    __nv_bfloat162 h23 = __floats2bfloat162_rn(v.z, v.w);
    uint2 hp; hp.x = *(uint32_t*)&h01; hp.y = *(uint32_t*)&h23;
    ((uint2*)g_Ah)[i] = hp;
}

// ---------------------------------------------------------------------------
// Prep W: Bh[n,k] = bf16(W[k,n])
// ---------------------------------------------------------------------------
__global__ __launch_bounds__(256) void prep_w_kernel(const float* __restrict__ W)
{
    __shared__ float t[32][33];
    int tx = threadIdx.x, ty = threadIdx.y;
    int x0 = blockIdx.x * 32, y0 = blockIdx.y * 32;
    #pragma unroll
    for (int r = 0; r < 4; r++)
        t[ty + r * 8][tx] = W[(y0 + ty + r * 8) * D + x0 + tx];
    __syncthreads();
    #pragma unroll
    for (int r = 0; r < 4; r++) {
        int n = x0 + ty + r * 8;
        int k = y0 + tx;
        g_Bh[n * D + k] = __float2bfloat16(t[tx][ty + r * 8]);
    }
}

// ---------------------------------------------------------------------------
// bf16 GEMM via mma.sync: Uh[:, n0base:n0base+256] = bf16( Ah @ Wh ) slice
// grid (2, 64), 256 threads, 3-stage cp.async (R12 shape + N-offset)
// ---------------------------------------------------------------------------
__global__ __launch_bounds__(256, 2) void dedicom_mma_kernel(int n0base)
{
    extern __shared__ char smem[];
    const int tid  = threadIdx.x;
    const int wid  = tid >> 5;
    const int lane = tid & 31;
    const int m0 = blockIdx.y * BM;
    const int n0 = n0base + blockIdx.x * BN;
    const uint32_t sbase = smem_to_u32(smem);

    const int wm = (wid & 3) * 16;
    const int wn = (wid >> 2) * 64;

    float acc[8][4];
    #pragma unroll
    for (int b = 0; b < 8; b++)
        #pragma unroll
        for (int c = 0; c < 4; c++) acc[b][c] = 0.f;

    auto load_stage = [&](int kc, int stg) {
        const int k0 = kc * BK;
        const uint32_t sb = sbase + stg * STAGE_BYTES;
        #pragma unroll
        for (int t = tid; t < 512; t += 256) {
            int m = t >> 3, j = t & 7;
            uint32_t sw = SMEM_SWIZZLE_128B((uint32_t)(m * 128 + j * 16));
            CP_ASYNC16(sb + A_OFF + sw, (const char*)(g_Ah + (m0 + m) * D + k0) + j * 16);
        }
        #pragma unroll
        for (int t = tid; t < 1024; t += 256) {
            int n = t >> 3, j = t & 7;
            uint32_t sw = SMEM_SWIZZLE_128B((uint32_t)(n * 128 + j * 16));
            CP_ASYNC16(sb + B_OFF + sw, (const char*)(g_Bh + (n0 + n) * D + k0) + j * 16);
        }
    };

    const int NKC = D / BK;
    load_stage(0, 0); CP_COMMIT();
    load_stage(1, 1); CP_COMMIT();

    for (int kc = 0; kc < NKC; kc++) {
        CP_WAIT(1);
        __syncthreads();

        const uint32_t sb = sbase + (kc % 3) * STAGE_BYTES;

        #pragma unroll
        for (int ks = 0; ks < BK / 16; ks++) {
            uint32_t a[4], bh[4][4];
            {
                uint32_t off = SMEM_SWIZZLE_128B(
                    (uint32_t)((wm + (lane & 15)) * 128 + ks * 32 + (lane >> 4) * 16));
                ldsm_x4(a[0], a[1], a[2], a[3], sb + A_OFF + off);
            }
            #pragma unroll
            for (int p = 0; p < 4; p++) {
                uint32_t off = SMEM_SWIZZLE_128B(
                    (uint32_t)((wn + p * 16 + ((lane >> 4) * 8) + (lane & 7)) * 128
                               + ks * 32 + ((lane >> 3) & 1) * 16));
                ldsm_x4(bh[p][0], bh[p][1], bh[p][2], bh[p][3], sb + B_OFF + off);
            }
            #pragma unroll
            for (int p = 0; p < 4; p++) {
                mma_bf16(acc[2 * p + 0], a, bh[p][0], bh[p][1]);
                mma_bf16(acc[2 * p + 1], a, bh[p][2], bh[p][3]);
            }
        }

        if (kc + 2 < NKC) { load_stage(kc + 2, (kc + 2) % 3); CP_COMMIT(); }
    }

    const int g  = lane >> 2;
    const int c2 = (lane & 3) * 2;
    const int row0 = m0 + wm + g;
    #pragma unroll
    for (int nt = 0; nt < 8; nt++) {
        const int col = wn + nt * 8 + c2;
        __nv_bfloat162 v0 = __floats2bfloat162_rn(acc[nt][0], acc[nt][1]);
        __nv_bfloat162 v1 = __floats2bfloat162_rn(acc[nt][2], acc[nt][3]);
        *(__nv_bfloat162*)(g_Uh + (long)row0 * D + n0 + col)       = v0;
        *(__nv_bfloat162*)(g_Uh + (long)(row0 + 8) * D + n0 + col) = v1;
    }
}

// ---------------------------------------------------------------------------
// Edge partial: one warp per edge, cols [c0, c0+256). One uint4/lane per side.
// Writes partial fp32 score to g_part[chunk * MAXEDGES + e].
// ---------------------------------------------------------------------------
__global__ __launch_bounds__(256) void edge_part_kernel(
    const int* __restrict__ edges, int n_edges, int c0, int chunk)
{
    const int w    = (blockIdx.x * blockDim.x + threadIdx.x) >> 5;
    const int lane = threadIdx.x & 31;
    if (w >= n_edges) return;

    const int r = edges[w];
    const int c = edges[n_edges + w];

    uint4 a = __ldg((const uint4*)(g_Uh + (long)r * D + c0) + lane);
    uint4 b = __ldg((const uint4*)(g_Ah + (long)c * D + c0) + lane);

    __nv_bfloat162 z2 = __floats2bfloat162_rn(0.f, 0.f);
    __nv_bfloat162 q0 = z2, q1 = z2, q2 = z2, q3 = z2;
    q0 = __hfma2(*(const __nv_bfloat162*)&a.x, *(const __nv_bfloat162*)&b.x, q0);
    q1 = __hfma2(*(const __nv_bfloat162*)&a.y, *(const __nv_bfloat162*)&b.y, q1);
    q2 = __hfma2(*(const __nv_bfloat162*)&a.z, *(const __nv_bfloat162*)&b.z, q2);
    q3 = __hfma2(*(const __nv_bfloat162*)&a.w, *(const __nv_bfloat162*)&b.w, q3);

    float2 f0 = __bfloat1622float2(q0);
    float2 f1 = __bfloat1622float2(q1);
    float2 f2 = __bfloat1622float2(q2);
    float2 f3 = __bfloat1622float2(q3);
    float acc = ((f0.x + f0.y) + (f1.x + f1.y)) + ((f2.x + f2.y) + (f3.x + f3.y));

    #pragma unroll
    for (int o = 16; o; o >>= 1) acc += __shfl_xor_sync(0xffffffffu, acc, o);

    if (lane == 0) g_part[chunk * MAXEDGES + w] = acc;
}

// ---------------------------------------------------------------------------
// Final: out[e] = sigmoid(part0[e] + part1[e])   (deterministic sum order)
// ---------------------------------------------------------------------------
__global__ __launch_bounds__(256) void edge_final_kernel(float* __restrict__ out, int n_edges)
{
    int e = blockIdx.x * 256 + threadIdx.x;
    if (e < n_edges)
        out[e] = 1.f / (1.f + __expf(-(g_part[e] + g_part[MAXEDGES + e])));
}

// ---------------------------------------------------------------------------
// Launch: fork-join capture — GEMM halves on a side stream overlap edge parts.
// ---------------------------------------------------------------------------
extern "C" void kernel_launch(void* const* d_in, const int* in_sizes, int n_in,
                              void* d_out, int out_size)
{
    const float* z     = (const float*)d_in[0];   // [4096, 512]
    const float* W     = (const float*)d_in[1];   // [512, 512]
    const float* ldiag = (const float*)d_in[2];   // [10, 512]
    const int*   edges = (const int*)d_in[3];     // [2, n_edges] int32
    const int*   idxp  = (const int*)d_in[4];     // scalar

    const int n_drugs = in_sizes[0] / D;
    const int n_edges = in_sizes[3] / 2;

    static bool init = false;
    static cudaStream_t sB;
    static cudaEvent_t ev0, evG0, evG1;
    if (!init) {
        cudaFuncSetAttribute(dedicom_mma_kernel,
                             cudaFuncAttributeMaxDynamicSharedMemorySize, SM_GEMM);
        cudaStreamCreateWithFlags(&sB, cudaStreamNonBlocking);
        cudaEventCreateWithFlags(&ev0,  cudaEventDisableTiming);
        cudaEventCreateWithFlags(&evG0, cudaEventDisableTiming);
        cudaEventCreateWithFlags(&evG1, cudaEventDisableTiming);
        init = true;
    }

    // preps on main stream
    prep_a_kernel<<<(n_drugs * D / 4 + 255) / 256, 256>>>(z, ldiag, idxp);
    prep_w_kernel<<<dim3(D / 32, D / 32), dim3(32, 8)>>>(W);

    // fork: GEMM halves on side stream
    cudaEventRecord(ev0, 0);
    cudaStreamWaitEvent(sB, ev0, 0);
    dedicom_mma_kernel<<<dim3(2, n_drugs / BM), 256, SM_GEMM, sB>>>(0);
    cudaEventRecord(evG0, sB);
    dedicom_mma_kernel<<<dim3(2, n_drugs / BM), 256, SM_GEMM, sB>>>(256);
    cudaEventRecord(evG1, sB);

    // main: edge partials (E0 overlaps GEMM half 1), then join + final
    const int eblocks = (n_edges + 7) / 8;
    cudaStreamWaitEvent(0, evG0, 0);
    edge_part_kernel<<<eblocks, 256>>>(edges, n_edges, 0, 0);
    cudaStreamWaitEvent(0, evG1, 0);
    edge_part_kernel<<<eblocks, 256>>>(edges, n_edges, 256, 1);
    edge_final_kernel<<<(n_edges + 255) / 256, 256>>>((float*)d_out, n_edges);
}

// round 15
// speedup vs baseline: 1.4239x; 1.3642x over previous
#include <cuda_runtime.h>
#include <cuda_bf16.h>
#include <cstdint>

#define D 512
#define NDRUGS 4096
#define BM 64
#define BN 128
#define BK 64

// ---------------- device scratch (allocation-free) ----------------
__device__ __align__(16) __nv_bfloat16  g_Uh[NDRUGS * D];    // 4 MB (U = (z*d)@W)
__device__ __align__(16) __nv_bfloat16  g_Ah[NDRUGS * D];    // 4 MB (bf16 of z*d)
__device__ __align__(16) __nv_bfloat16  g_Bh[D * D];         // 512 KB (W^T bf16)

// ---------------- helpers ----------------
__device__ __forceinline__ uint32_t smem_to_u32(const void* p) {
    uint32_t a;
    asm("{ .reg .u64 t; cvta.to.shared.u64 t, %1; cvt.u32.u64 %0, t; }" : "=r"(a) : "l"(p));
    return a;
}
#define SMEM_SWIZZLE_128B(o) ((o) ^ (((o) >> 3) & 0x70))

#define CP_ASYNC16(dst, src) \
    asm volatile("cp.async.cg.shared.global [%0], [%1], 16;" :: "r"(dst), "l"(src))
#define CP_COMMIT() asm volatile("cp.async.commit_group;" ::: "memory")
#define CP_WAIT(n)  asm volatile("cp.async.wait_group %0;" :: "n"(n) : "memory")

__device__ __forceinline__ void ldsm_x4(uint32_t& r0, uint32_t& r1, uint32_t& r2, uint32_t& r3,
                                        uint32_t addr) {
    asm volatile("ldmatrix.sync.aligned.m8n8.x4.shared.b16 {%0,%1,%2,%3}, [%4];"
                 : "=r"(r0), "=r"(r1), "=r"(r2), "=r"(r3) : "r"(addr));
}
__device__ __forceinline__ void mma_bf16(float* c, const uint32_t* a, uint32_t b0, uint32_t b1) {
    asm volatile("mma.sync.aligned.m16n8k16.row.col.f32.bf16.bf16.f32 "
                 "{%0,%1,%2,%3}, {%4,%5,%6,%7}, {%8,%9}, {%0,%1,%2,%3};"
                 : "+f"(c[0]), "+f"(c[1]), "+f"(c[2]), "+f"(c[3])
                 : "r"(a[0]), "r"(a[1]), "r"(a[2]), "r"(a[3]), "r"(b0), "r"(b1));
}

// GEMM SMEM: 3 stages x (A 8K | B 16K) = 72 KB
#define STAGE_BYTES 24576
#define A_OFF 0
#define B_OFF 8192
#define SM_GEMM (3 * STAGE_BYTES)

// prep dispatch: blocks [0, PREP_A_BLOCKS) do A, the rest do W transpose
#define PREP_A_BLOCKS (NDRUGS * D / 4 / 256)     // 2048
#define PREP_W_BLOCKS ((D / 32) * (D / 32))      // 256

// ---------------------------------------------------------------------------
// Merged prep: Ah = bf16(z*d)  |  Bh[n,k] = bf16(W[k,n])
// ---------------------------------------------------------------------------
__global__ __launch_bounds__(256) void prep_kernel(
    const float* __restrict__ z, const float* __restrict__ W,
    const float* __restrict__ ldiag, const int* __restrict__ idxp)
{
    if (blockIdx.x < PREP_A_BLOCKS) {
        const float* dp = ldiag + idxp[0] * D;
        int i = blockIdx.x * 256 + threadIdx.x;
        int k4 = (i & (D / 4 - 1)) << 2;
        float4 v = ((const float4*)z)[i];
        v.x *= dp[k4 + 0]; v.y *= dp[k4 + 1]; v.z *= dp[k4 + 2]; v.w *= dp[k4 + 3];

        __nv_bfloat162 h01 = __floats2bfloat162_rn(v.x, v.y);
        __nv_bfloat162 h23 = __floats2bfloat162_rn(v.z, v.w);
        uint2 hp; hp.x = *(uint32_t*)&h01; hp.y = *(uint32_t*)&h23;
        ((uint2*)g_Ah)[i] = hp;
    } else {
        __shared__ float t[32][33];
        int b  = blockIdx.x - PREP_A_BLOCKS;
        int x0 = (b & 15) * 32, y0 = (b >> 4) * 32;
        int tx = threadIdx.x & 31, ty = threadIdx.x >> 5;   // 32 x 8
        #pragma unroll
        for (int r = 0; r < 4; r++)
            t[ty + r * 8][tx] = W[(y0 + ty + r * 8) * D + x0 + tx];
        __syncthreads();
        #pragma unroll
        for (int r = 0; r < 4; r++) {
            int n = x0 + ty + r * 8;
            int k = y0 + tx;
            g_Bh[n * D + k] = __float2bfloat16(t[tx][ty + r * 8]);
        }
    }
}

// ---------------------------------------------------------------------------
// bf16 GEMM via mma.sync: Uh = bf16( Ah @ Wh )
// grid (D/BN=4, NDRUGS/BM=64) = 256 CTAs, 256 threads, 3-stage cp.async
// warp layout: 4m x 2n, warp tile 16 x 64   (R12 proven shape)
// ---------------------------------------------------------------------------
__global__ __launch_bounds__(256, 2) void dedicom_mma_kernel()
{
    extern __shared__ char smem[];
    const int tid  = threadIdx.x;
    const int wid  = tid >> 5;
    const int lane = tid & 31;
    const int m0 = blockIdx.y * BM;
    const int n0 = blockIdx.x * BN;
    const uint32_t sbase = smem_to_u32(smem);

    const int wm = (wid & 3) * 16;
    const int wn = (wid >> 2) * 64;

    float acc[8][4];
    #pragma unroll
    for (int b = 0; b < 8; b++)
        #pragma unroll
        for (int c = 0; c < 4; c++) acc[b][c] = 0.f;

    auto load_stage = [&](int kc, int stg) {
        const int k0 = kc * BK;
        const uint32_t sb = sbase + stg * STAGE_BYTES;
        #pragma unroll
        for (int t = tid; t < 512; t += 256) {
            int m = t >> 3, j = t & 7;
            uint32_t sw = SMEM_SWIZZLE_128B((uint32_t)(m * 128 + j * 16));
            CP_ASYNC16(sb + A_OFF + sw, (const char*)(g_Ah + (m0 + m) * D + k0) + j * 16);
        }
        #pragma unroll
        for (int t = tid; t < 1024; t += 256) {
            int n = t >> 3, j = t & 7;
            uint32_t sw = SMEM_SWIZZLE_128B((uint32_t)(n * 128 + j * 16));
            CP_ASYNC16(sb + B_OFF + sw, (const char*)(g_Bh + (n0 + n) * D + k0) + j * 16);
        }
    };

    const int NKC = D / BK;
    load_stage(0, 0); CP_COMMIT();
    load_stage(1, 1); CP_COMMIT();

    for (int kc = 0; kc < NKC; kc++) {
        CP_WAIT(1);
        __syncthreads();

        const uint32_t sb = sbase + (kc % 3) * STAGE_BYTES;

        #pragma unroll
        for (int ks = 0; ks < BK / 16; ks++) {
            uint32_t a[4], bh[4][4];
            {
                uint32_t off = SMEM_SWIZZLE_128B(
                    (uint32_t)((wm + (lane & 15)) * 128 + ks * 32 + (lane >> 4) * 16));
                ldsm_x4(a[0], a[1], a[2], a[3], sb + A_OFF + off);
            }
            #pragma unroll
            for (int p = 0; p < 4; p++) {
                uint32_t off = SMEM_SWIZZLE_128B(
                    (uint32_t)((wn + p * 16 + ((lane >> 4) * 8) + (lane & 7)) * 128
                               + ks * 32 + ((lane >> 3) & 1) * 16));
                ldsm_x4(bh[p][0], bh[p][1], bh[p][2], bh[p][3], sb + B_OFF + off);
            }
            #pragma unroll
            for (int p = 0; p < 4; p++) {
                mma_bf16(acc[2 * p + 0], a, bh[p][0], bh[p][1]);
                mma_bf16(acc[2 * p + 1], a, bh[p][2], bh[p][3]);
            }
        }

        if (kc + 2 < NKC) { load_stage(kc + 2, (kc + 2) % 3); CP_COMMIT(); }
    }

    const int g  = lane >> 2;
    const int c2 = (lane & 3) * 2;
    const int row0 = m0 + wm + g;
    #pragma unroll
    for (int nt = 0; nt < 8; nt++) {
        const int col = wn + nt * 8 + c2;
        __nv_bfloat162 v0 = __floats2bfloat162_rn(acc[nt][0], acc[nt][1]);
        __nv_bfloat162 v1 = __floats2bfloat162_rn(acc[nt][2], acc[nt][3]);
        *(__nv_bfloat162*)(g_Uh + (long)row0 * D + n0 + col)       = v0;
        *(__nv_bfloat162*)(g_Uh + (long)(row0 + 8) * D + n0 + col) = v1;
    }
}

// ---------------------------------------------------------------------------
// Phase 2 (flat, proven 23.8 us @ LTS cap): one warp per edge.
// ---------------------------------------------------------------------------
__global__ __launch_bounds__(256) void dedicom_edge_kernel(
    const int* __restrict__ edges,
    float* __restrict__ out,
    int n_edges)
{
    const int w    = (blockIdx.x * blockDim.x + threadIdx.x) >> 5;
    const int lane = threadIdx.x & 31;
    if (w >= n_edges) return;

    const int r = edges[w];
    const int c = edges[n_edges + w];

    const uint4* vr = (const uint4*)(g_Uh + (long)r * D);
    const uint4* zc = (const uint4*)(g_Ah + (long)c * D);

    __nv_bfloat162 z2 = __floats2bfloat162_rn(0.f, 0.f);
    __nv_bfloat162 q0 = z2, q1 = z2, q2 = z2, q3 = z2;

    #pragma unroll
    for (int i = 0; i < 2; i++) {
        uint4 a = __ldg(&vr[lane + i * 32]);
        uint4 b = __ldg(&zc[lane + i * 32]);
        q0 = __hfma2(*(const __nv_bfloat162*)&a.x, *(const __nv_bfloat162*)&b.x, q0);
        q1 = __hfma2(*(const __nv_bfloat162*)&a.y, *(const __nv_bfloat162*)&b.y, q1);
        q2 = __hfma2(*(const __nv_bfloat162*)&a.z, *(const __nv_bfloat162*)&b.z, q2);
        q3 = __hfma2(*(const __nv_bfloat162*)&a.w, *(const __nv_bfloat162*)&b.w, q3);
    }

    float2 f0 = __bfloat1622float2(q0);
    float2 f1 = __bfloat1622float2(q1);
    float2 f2 = __bfloat1622float2(q2);
    float2 f3 = __bfloat1622float2(q3);
    float acc = ((f0.x + f0.y) + (f1.x + f1.y)) + ((f2.x + f2.y) + (f3.x + f3.y));

    #pragma unroll
    for (int o = 16; o; o >>= 1) acc += __shfl_xor_sync(0xffffffffu, acc, o);

    if (lane == 0) out[w] = 1.f / (1.f + __expf(-acc));
}

// ---------------------------------------------------------------------------
// Launch: 3 kernels, single stream, serial (overlap proven net-negative)
// ---------------------------------------------------------------------------
extern "C" void kernel_launch(void* const* d_in, const int* in_sizes, int n_in,
                              void* d_out, int out_size)
{
    const float* z     = (const float*)d_in[0];   // [4096, 512]
    const float* W     = (const float*)d_in[1];   // [512, 512]
    const float* ldiag = (const float*)d_in[2];   // [10, 512]
    const int*   edges = (const int*)d_in[3];     // [2, n_edges] int32
    const int*   idxp  = (const int*)d_in[4];     // scalar

    const int n_drugs = in_sizes[0] / D;
    const int n_edges = in_sizes[3] / 2;

    static int smem_set = 0;
    if (!smem_set) {
        cudaFuncSetAttribute(dedicom_mma_kernel,
                             cudaFuncAttributeMaxDynamicSharedMemorySize, SM_GEMM);
        smem_set = 1;
    }

    prep_kernel<<<PREP_A_BLOCKS + PREP_W_BLOCKS, 256>>>(z, W, ldiag, idxp);

    dim3 gm(D / BN, n_drugs / BM);
    dedicom_mma_kernel<<<gm, 256, SM_GEMM>>>();

    int blocks = (n_edges + 7) / 8;
    dedicom_edge_kernel<<<blocks, 256>>>(edges, (float*)d_out, n_edges);
}

// round 16
// speedup vs baseline: 1.4937x; 1.0491x over previous
#include <cuda_runtime.h>
#include <cuda_bf16.h>
#include <cstdint>

#define D 512
#define NDRUGS 4096
#define BM 64
#define BN 128
#define BK 64

// ---------------- device scratch (allocation-free) ----------------
__device__ __align__(16) __nv_bfloat16  g_Uh[NDRUGS * D];    // 4 MB (U = (z*d)@W)
__device__ __align__(16) __nv_bfloat16  g_Ah[NDRUGS * D];    // 4 MB (bf16 of z*d)
__device__ __align__(16) __nv_bfloat16  g_Bh[D * D];         // 512 KB (W^T bf16)

// ---------------- helpers ----------------
__device__ __forceinline__ uint32_t smem_to_u32(const void* p) {
    uint32_t a;
    asm("{ .reg .u64 t; cvta.to.shared.u64 t, %1; cvt.u32.u64 %0, t; }" : "=r"(a) : "l"(p));
    return a;
}
#define SMEM_SWIZZLE_128B(o) ((o) ^ (((o) >> 3) & 0x70))

#define CP_ASYNC16(dst, src) \
    asm volatile("cp.async.cg.shared.global [%0], [%1], 16;" :: "r"(dst), "l"(src))
#define CP_COMMIT() asm volatile("cp.async.commit_group;" ::: "memory")
#define CP_WAIT(n)  asm volatile("cp.async.wait_group %0;" :: "n"(n) : "memory")

__device__ __forceinline__ void ldsm_x4(uint32_t& r0, uint32_t& r1, uint32_t& r2, uint32_t& r3,
                                        uint32_t addr) {
    asm volatile("ldmatrix.sync.aligned.m8n8.x4.shared.b16 {%0,%1,%2,%3}, [%4];"
                 : "=r"(r0), "=r"(r1), "=r"(r2), "=r"(r3) : "r"(addr));
}
__device__ __forceinline__ void mma_bf16(float* c, const uint32_t* a, uint32_t b0, uint32_t b1) {
    asm volatile("mma.sync.aligned.m16n8k16.row.col.f32.bf16.bf16.f32 "
                 "{%0,%1,%2,%3}, {%4,%5,%6,%7}, {%8,%9}, {%0,%1,%2,%3};"
                 : "+f"(c[0]), "+f"(c[1]), "+f"(c[2]), "+f"(c[3])
                 : "r"(a[0]), "r"(a[1]), "r"(a[2]), "r"(a[3]), "r"(b0), "r"(b1));
}

// GEMM SMEM: 3 stages x (A 8K | B 16K) = 72 KB
#define STAGE_BYTES 24576
#define A_OFF 0
#define B_OFF 8192
#define SM_GEMM (3 * STAGE_BYTES)

// prep dispatch: blocks [0, PREP_A_BLOCKS) do A (8 floats/thread), rest do W
#define PREP_A_BLOCKS (NDRUGS * D / 8 / 256)     // 1024
#define PREP_W_BLOCKS ((D / 32) * (D / 32))      // 256

// ---------------------------------------------------------------------------
// Merged prep: Ah = bf16(z*d)  |  Bh[n,k] = bf16(W[k,n])
// A side: 2 float4 of z + 2 float4 of dp per thread -> 1 STG.128 of 8 bf16.
// (5 LSU ops per 8 floats vs 14 before -> LSU-bound time drops ~2.8x)
// ---------------------------------------------------------------------------
__global__ __launch_bounds__(256) void prep_kernel(
    const float* __restrict__ z, const float* __restrict__ W,
    const float* __restrict__ ldiag, const int* __restrict__ idxp)
{
    if (blockIdx.x < PREP_A_BLOCKS) {
        const float4* dp4 = (const float4*)(ldiag + idxp[0] * D);
        int i  = blockIdx.x * 256 + threadIdx.x;    // 8-float group index
        int j0 = 2 * i;                              // float4 index (even)
        int c0 = j0 & (D / 4 - 1);                   // float4 col, even -> c0+1 same row

        float4 v0 = ((const float4*)z)[j0];
        float4 v1 = ((const float4*)z)[j0 + 1];
        float4 d0 = dp4[c0];
        float4 d1 = dp4[c0 + 1];

        v0.x *= d0.x; v0.y *= d0.y; v0.z *= d0.z; v0.w *= d0.w;
        v1.x *= d1.x; v1.y *= d1.y; v1.z *= d1.z; v1.w *= d1.w;

        __nv_bfloat162 h0 = __floats2bfloat162_rn(v0.x, v0.y);
        __nv_bfloat162 h1 = __floats2bfloat162_rn(v0.z, v0.w);
        __nv_bfloat162 h2 = __floats2bfloat162_rn(v1.x, v1.y);
        __nv_bfloat162 h3 = __floats2bfloat162_rn(v1.z, v1.w);
        uint4 o;
        o.x = *(uint32_t*)&h0; o.y = *(uint32_t*)&h1;
        o.z = *(uint32_t*)&h2; o.w = *(uint32_t*)&h3;
        ((uint4*)g_Ah)[i] = o;
    } else {
        __shared__ float t[32][33];
        int b  = blockIdx.x - PREP_A_BLOCKS;
        int x0 = (b & 15) * 32, y0 = (b >> 4) * 32;
        int tx = threadIdx.x & 31, ty = threadIdx.x >> 5;   // 32 x 8
        #pragma unroll
        for (int r = 0; r < 4; r++)
            t[ty + r * 8][tx] = W[(y0 + ty + r * 8) * D + x0 + tx];
        __syncthreads();
        #pragma unroll
        for (int r = 0; r < 4; r++) {
            int n = x0 + ty + r * 8;
            int k = y0 + tx;
            g_Bh[n * D + k] = __float2bfloat16(t[tx][ty + r * 8]);
        }
    }
}

// ---------------------------------------------------------------------------
// bf16 GEMM via mma.sync: Uh = bf16( Ah @ Wh )
// grid (D/BN=4, NDRUGS/BM=64) = 256 CTAs, 256 threads, 3-stage cp.async
// warp layout: 4m x 2n, warp tile 16 x 64   (R12 proven shape)
// ---------------------------------------------------------------------------
__global__ __launch_bounds__(256, 2) void dedicom_mma_kernel()
{
    extern __shared__ char smem[];
    const int tid  = threadIdx.x;
    const int wid  = tid >> 5;
    const int lane = tid & 31;
    const int m0 = blockIdx.y * BM;
    const int n0 = blockIdx.x * BN;
    const uint32_t sbase = smem_to_u32(smem);

    const int wm = (wid & 3) * 16;
    const int wn = (wid >> 2) * 64;

    float acc[8][4];
    #pragma unroll
    for (int b = 0; b < 8; b++)
        #pragma unroll
        for (int c = 0; c < 4; c++) acc[b][c] = 0.f;

    auto load_stage = [&](int kc, int stg) {
        const int k0 = kc * BK;
        const uint32_t sb = sbase + stg * STAGE_BYTES;
        #pragma unroll
        for (int t = tid; t < 512; t += 256) {
            int m = t >> 3, j = t & 7;
            uint32_t sw = SMEM_SWIZZLE_128B((uint32_t)(m * 128 + j * 16));
            CP_ASYNC16(sb + A_OFF + sw, (const char*)(g_Ah + (m0 + m) * D + k0) + j * 16);
        }
        #pragma unroll
        for (int t = tid; t < 1024; t += 256) {
            int n = t >> 3, j = t & 7;
            uint32_t sw = SMEM_SWIZZLE_128B((uint32_t)(n * 128 + j * 16));
            CP_ASYNC16(sb + B_OFF + sw, (const char*)(g_Bh + (n0 + n) * D + k0) + j * 16);
        }
    };

    const int NKC = D / BK;
    load_stage(0, 0); CP_COMMIT();
    load_stage(1, 1); CP_COMMIT();

    for (int kc = 0; kc < NKC; kc++) {
        CP_WAIT(1);
        __syncthreads();

        const uint32_t sb = sbase + (kc % 3) * STAGE_BYTES;

        #pragma unroll
        for (int ks = 0; ks < BK / 16; ks++) {
            uint32_t a[4], bh[4][4];
            {
                uint32_t off = SMEM_SWIZZLE_128B(
                    (uint32_t)((wm + (lane & 15)) * 128 + ks * 32 + (lane >> 4) * 16));
                ldsm_x4(a[0], a[1], a[2], a[3], sb + A_OFF + off);
            }
            #pragma unroll
            for (int p = 0; p < 4; p++) {
                uint32_t off = SMEM_SWIZZLE_128B(
                    (uint32_t)((wn + p * 16 + ((lane >> 4) * 8) + (lane & 7)) * 128
                               + ks * 32 + ((lane >> 3) & 1) * 16));
                ldsm_x4(bh[p][0], bh[p][1], bh[p][2], bh[p][3], sb + B_OFF + off);
            }
            #pragma unroll
            for (int p = 0; p < 4; p++) {
                mma_bf16(acc[2 * p + 0], a, bh[p][0], bh[p][1]);
                mma_bf16(acc[2 * p + 1], a, bh[p][2], bh[p][3]);
            }
        }

        if (kc + 2 < NKC) { load_stage(kc + 2, (kc + 2) % 3); CP_COMMIT(); }
    }

    const int g  = lane >> 2;
    const int c2 = (lane & 3) * 2;
    const int row0 = m0 + wm + g;
    #pragma unroll
    for (int nt = 0; nt < 8; nt++) {
        const int col = wn + nt * 8 + c2;
        __nv_bfloat162 v0 = __floats2bfloat162_rn(acc[nt][0], acc[nt][1]);
        __nv_bfloat162 v1 = __floats2bfloat162_rn(acc[nt][2], acc[nt][3]);
        *(__nv_bfloat162*)(g_Uh + (long)row0 * D + n0 + col)       = v0;
        *(__nv_bfloat162*)(g_Uh + (long)(row0 + 8) * D + n0 + col) = v1;
    }
}

// ---------------------------------------------------------------------------
// Phase 2 (flat, proven 23.8 us @ LTS cap): one warp per edge.
// ---------------------------------------------------------------------------
__global__ __launch_bounds__(256) void dedicom_edge_kernel(
    const int* __restrict__ edges,
    float* __restrict__ out,
    int n_edges)
{
    const int w    = (blockIdx.x * blockDim.x + threadIdx.x) >> 5;
    const int lane = threadIdx.x & 31;
    if (w >= n_edges) return;

    const int r = edges[w];
    const int c = edges[n_edges + w];

    const uint4* vr = (const uint4*)(g_Uh + (long)r * D);
    const uint4* zc = (const uint4*)(g_Ah + (long)c * D);

    __nv_bfloat162 z2 = __floats2bfloat162_rn(0.f, 0.f);
    __nv_bfloat162 q0 = z2, q1 = z2, q2 = z2, q3 = z2;

    #pragma unroll
    for (int i = 0; i < 2; i++) {
        uint4 a = __ldg(&vr[lane + i * 32]);
        uint4 b = __ldg(&zc[lane + i * 32]);
        q0 = __hfma2(*(const __nv_bfloat162*)&a.x, *(const __nv_bfloat162*)&b.x, q0);
        q1 = __hfma2(*(const __nv_bfloat162*)&a.y, *(const __nv_bfloat162*)&b.y, q1);
        q2 = __hfma2(*(const __nv_bfloat162*)&a.z, *(const __nv_bfloat162*)&b.z, q2);
        q3 = __hfma2(*(const __nv_bfloat162*)&a.w, *(const __nv_bfloat162*)&b.w, q3);
    }

    float2 f0 = __bfloat1622float2(q0);
    float2 f1 = __bfloat1622float2(q1);
    float2 f2 = __bfloat1622float2(q2);
    float2 f3 = __bfloat1622float2(q3);
    float acc = ((f0.x + f0.y) + (f1.x + f1.y)) + ((f2.x + f2.y) + (f3.x + f3.y));

    #pragma unroll
    for (int o = 16; o; o >>= 1) acc += __shfl_xor_sync(0xffffffffu, acc, o);

    if (lane == 0) out[w] = 1.f / (1.f + __expf(-acc));
}

// ---------------------------------------------------------------------------
// Launch: 3 kernels, single stream, serial (overlap proven net-negative)
// ---------------------------------------------------------------------------
extern "C" void kernel_launch(void* const* d_in, const int* in_sizes, int n_in,
                              void* d_out, int out_size)
{
    const float* z     = (const float*)d_in[0];   // [4096, 512]
    const float* W     = (const float*)d_in[1];   // [512, 512]
    const float* ldiag = (const float*)d_in[2];   // [10, 512]
    const int*   edges = (const int*)d_in[3];     // [2, n_edges] int32
    const int*   idxp  = (const int*)d_in[4];     // scalar

    const int n_drugs = in_sizes[0] / D;
    const int n_edges = in_sizes[3] / 2;

    static int smem_set = 0;
    if (!smem_set) {
        cudaFuncSetAttribute(dedicom_mma_kernel,
                             cudaFuncAttributeMaxDynamicSharedMemorySize, SM_GEMM);
        smem_set = 1;
    }

    prep_kernel<<<PREP_A_BLOCKS + PREP_W_BLOCKS, 256>>>(z, W, ldiag, idxp);

    dim3 gm(D / BN, n_drugs / BM);
    dedicom_mma_kernel<<<gm, 256, SM_GEMM>>>();

    int blocks = (n_edges + 7) / 8;
    dedicom_edge_kernel<<<blocks, 256>>>(edges, (float*)d_out, n_edges);
}

// round 17
// speedup vs baseline: 1.4952x; 1.0010x over previous
#include <cuda_runtime.h>
#include <cuda_bf16.h>
#include <cstdint>

#define D 512
#define NDRUGS 4096
#define BM 64
#define BN 128
#define BK 64

// ---------------- device scratch (allocation-free) ----------------
__device__ __align__(16) __nv_bfloat16  g_Uh[NDRUGS * D];    // 4 MB (U = (z*d)@W)
__device__ __align__(16) __nv_bfloat16  g_Ah[NDRUGS * D];    // 4 MB (bf16 of z*d)
__device__ __align__(16) __nv_bfloat16  g_Bh[D * D];         // 512 KB (W^T bf16)

// ---------------- helpers ----------------
__device__ __forceinline__ uint32_t smem_to_u32(const void* p) {
    uint32_t a;
    asm("{ .reg .u64 t; cvta.to.shared.u64 t, %1; cvt.u32.u64 %0, t; }" : "=r"(a) : "l"(p));
    return a;
}
#define SMEM_SWIZZLE_128B(o) ((o) ^ (((o) >> 3) & 0x70))

#define CP_ASYNC16(dst, src) \
    asm volatile("cp.async.cg.shared.global [%0], [%1], 16;" :: "r"(dst), "l"(src))
#define CP_COMMIT() asm volatile("cp.async.commit_group;" ::: "memory")
#define CP_WAIT(n)  asm volatile("cp.async.wait_group %0;" :: "n"(n) : "memory")

__device__ __forceinline__ void ldsm_x4(uint32_t& r0, uint32_t& r1, uint32_t& r2, uint32_t& r3,
                                        uint32_t addr) {
    asm volatile("ldmatrix.sync.aligned.m8n8.x4.shared.b16 {%0,%1,%2,%3}, [%4];"
                 : "=r"(r0), "=r"(r1), "=r"(r2), "=r"(r3) : "r"(addr));
}
__device__ __forceinline__ void mma_bf16(float* c, const uint32_t* a, uint32_t b0, uint32_t b1) {
    asm volatile("mma.sync.aligned.m16n8k16.row.col.f32.bf16.bf16.f32 "
                 "{%0,%1,%2,%3}, {%4,%5,%6,%7}, {%8,%9}, {%0,%1,%2,%3};"
                 : "+f"(c[0]), "+f"(c[1]), "+f"(c[2]), "+f"(c[3])
                 : "r"(a[0]), "r"(a[1]), "r"(a[2]), "r"(a[3]), "r"(b0), "r"(b1));
}

// GEMM SMEM: 3 stages x (A 8K | B 16K) = 72 KB
#define STAGE_BYTES 24576
#define A_OFF 0
#define B_OFF 8192
#define SM_GEMM (3 * STAGE_BYTES)

// prep dispatch: blocks [0, PREP_A_BLOCKS) do A (1 float4/thread), rest do W
#define PREP_A_BLOCKS (NDRUGS * D / 4 / 256)     // 2048
#define PREP_W_BLOCKS ((D / 32) * (D / 32))      // 256

// ---------------------------------------------------------------------------
// Merged prep: Ah = bf16(z*d)  |  Bh[n,k] = bf16(W[k,n])
// A side: fully coalesced — per warp: z LDG.128 (4 lines) + dp LDG.128
// (4 lines, lanes consecutive) + STG.64 (2 wf) = 10 L1tex wavefronts
// (vs 52 in the previous pairing scheme).
// ---------------------------------------------------------------------------
__global__ __launch_bounds__(256) void prep_kernel(
    const float* __restrict__ z, const float* __restrict__ W,
    const float* __restrict__ ldiag, const int* __restrict__ idxp)
{
    if (blockIdx.x < PREP_A_BLOCKS) {
        const float4* dp4 = (const float4*)(ldiag + idxp[0] * D);
        int i = blockIdx.x * 256 + threadIdx.x;      // float4 index, consecutive per lane
        float4 v = ((const float4*)z)[i];
        float4 d = dp4[i & (D / 4 - 1)];             // lanes consecutive -> coalesced
        v.x *= d.x; v.y *= d.y; v.z *= d.z; v.w *= d.w;

        __nv_bfloat162 h0 = __floats2bfloat162_rn(v.x, v.y);
        __nv_bfloat162 h1 = __floats2bfloat162_rn(v.z, v.w);
        uint2 o; o.x = *(uint32_t*)&h0; o.y = *(uint32_t*)&h1;
        ((uint2*)g_Ah)[i] = o;
    } else {
        __shared__ float t[32][33];
        int b  = blockIdx.x - PREP_A_BLOCKS;
        int x0 = (b & 15) * 32, y0 = (b >> 4) * 32;
        int tx = threadIdx.x & 31, ty = threadIdx.x >> 5;   // 32 x 8
        #pragma unroll
        for (int r = 0; r < 4; r++)
            t[ty + r * 8][tx] = W[(y0 + ty + r * 8) * D + x0 + tx];
        __syncthreads();
        #pragma unroll
        for (int r = 0; r < 4; r++) {
            int n = x0 + ty + r * 8;
            int k = y0 + tx;
            g_Bh[n * D + k] = __float2bfloat16(t[tx][ty + r * 8]);
        }
    }
}

// ---------------------------------------------------------------------------
// bf16 GEMM via mma.sync: Uh = bf16( Ah @ Wh )
// grid (D/BN=4, NDRUGS/BM=64) = 256 CTAs, 256 threads, 3-stage cp.async
// warp layout: 4m x 2n, warp tile 16 x 64   (R12 proven shape)
// ---------------------------------------------------------------------------
__global__ __launch_bounds__(256, 2) void dedicom_mma_kernel()
{
    extern __shared__ char smem[];
    const int tid  = threadIdx.x;
    const int wid  = tid >> 5;
    const int lane = tid & 31;
    const int m0 = blockIdx.y * BM;
    const int n0 = blockIdx.x * BN;
    const uint32_t sbase = smem_to_u32(smem);

    const int wm = (wid & 3) * 16;
    const int wn = (wid >> 2) * 64;

    float acc[8][4];
    #pragma unroll
    for (int b = 0; b < 8; b++)
        #pragma unroll
        for (int c = 0; c < 4; c++) acc[b][c] = 0.f;

    auto load_stage = [&](int kc, int stg) {
        const int k0 = kc * BK;
        const uint32_t sb = sbase + stg * STAGE_BYTES;
        #pragma unroll
        for (int t = tid; t < 512; t += 256) {
            int m = t >> 3, j = t & 7;
            uint32_t sw = SMEM_SWIZZLE_128B((uint32_t)(m * 128 + j * 16));
            CP_ASYNC16(sb + A_OFF + sw, (const char*)(g_Ah + (m0 + m) * D + k0) + j * 16);
        }
        #pragma unroll
        for (int t = tid; t < 1024; t += 256) {
            int n = t >> 3, j = t & 7;
            uint32_t sw = SMEM_SWIZZLE_128B((uint32_t)(n * 128 + j * 16));
            CP_ASYNC16(sb + B_OFF + sw, (const char*)(g_Bh + (n0 + n) * D + k0) + j * 16);
        }
    };

    const int NKC = D / BK;
    load_stage(0, 0); CP_COMMIT();
    load_stage(1, 1); CP_COMMIT();

    for (int kc = 0; kc < NKC; kc++) {
        CP_WAIT(1);
        __syncthreads();

        const uint32_t sb = sbase + (kc % 3) * STAGE_BYTES;

        #pragma unroll
        for (int ks = 0; ks < BK / 16; ks++) {
            uint32_t a[4], bh[4][4];
            {
                uint32_t off = SMEM_SWIZZLE_128B(
                    (uint32_t)((wm + (lane & 15)) * 128 + ks * 32 + (lane >> 4) * 16));
                ldsm_x4(a[0], a[1], a[2], a[3], sb + A_OFF + off);
            }
            #pragma unroll
            for (int p = 0; p < 4; p++) {
                uint32_t off = SMEM_SWIZZLE_128B(
                    (uint32_t)((wn + p * 16 + ((lane >> 4) * 8) + (lane & 7)) * 128
                               + ks * 32 + ((lane >> 3) & 1) * 16));
                ldsm_x4(bh[p][0], bh[p][1], bh[p][2], bh[p][3], sb + B_OFF + off);
            }
            #pragma unroll
            for (int p = 0; p < 4; p++) {
                mma_bf16(acc[2 * p + 0], a, bh[p][0], bh[p][1]);
                mma_bf16(acc[2 * p + 1], a, bh[p][2], bh[p][3]);
            }
        }

        if (kc + 2 < NKC) { load_stage(kc + 2, (kc + 2) % 3); CP_COMMIT(); }
    }

    const int g  = lane >> 2;
    const int c2 = (lane & 3) * 2;
    const int row0 = m0 + wm + g;
    #pragma unroll
    for (int nt = 0; nt < 8; nt++) {
        const int col = wn + nt * 8 + c2;
        __nv_bfloat162 v0 = __floats2bfloat162_rn(acc[nt][0], acc[nt][1]);
        __nv_bfloat162 v1 = __floats2bfloat162_rn(acc[nt][2], acc[nt][3]);
        *(__nv_bfloat162*)(g_Uh + (long)row0 * D + n0 + col)       = v0;
        *(__nv_bfloat162*)(g_Uh + (long)(row0 + 8) * D + n0 + col) = v1;
    }
}

// ---------------------------------------------------------------------------
// Phase 2 (flat, proven 23.8 us @ LTS cap): one warp per edge.
// ---------------------------------------------------------------------------
__global__ __launch_bounds__(256) void dedicom_edge_kernel(
    const int* __restrict__ edges,
    float* __restrict__ out,
    int n_edges)
{
    const int w    = (blockIdx.x * blockDim.x + threadIdx.x) >> 5;
    const int lane = threadIdx.x & 31;
    if (w >= n_edges) return;

    const int r = edges[w];
    const int c = edges[n_edges + w];

    const uint4* vr = (const uint4*)(g_Uh + (long)r * D);
    const uint4* zc = (const uint4*)(g_Ah + (long)c * D);

    __nv_bfloat162 z2 = __floats2bfloat162_rn(0.f, 0.f);
    __nv_bfloat162 q0 = z2, q1 = z2, q2 = z2, q3 = z2;

    #pragma unroll
    for (int i = 0; i < 2; i++) {
        uint4 a = __ldg(&vr[lane + i * 32]);
        uint4 b = __ldg(&zc[lane + i * 32]);
        q0 = __hfma2(*(const __nv_bfloat162*)&a.x, *(const __nv_bfloat162*)&b.x, q0);
        q1 = __hfma2(*(const __nv_bfloat162*)&a.y, *(const __nv_bfloat162*)&b.y, q1);
        q2 = __hfma2(*(const __nv_bfloat162*)&a.z, *(const __nv_bfloat162*)&b.z, q2);
        q3 = __hfma2(*(const __nv_bfloat162*)&a.w, *(const __nv_bfloat162*)&b.w, q3);
    }

    float2 f0 = __bfloat1622float2(q0);
    float2 f1 = __bfloat1622float2(q1);
    float2 f2 = __bfloat1622float2(q2);
    float2 f3 = __bfloat1622float2(q3);
    float acc = ((f0.x + f0.y) + (f1.x + f1.y)) + ((f2.x + f2.y) + (f3.x + f3.y));

    #pragma unroll
    for (int o = 16; o; o >>= 1) acc += __shfl_xor_sync(0xffffffffu, acc, o);

    if (lane == 0) out[w] = 1.f / (1.f + __expf(-acc));
}

// ---------------------------------------------------------------------------
// Launch: 3 kernels, single stream, serial (overlap proven net-negative)
// ---------------------------------------------------------------------------
extern "C" void kernel_launch(void* const* d_in, const int* in_sizes, int n_in,
                              void* d_out, int out_size)
{
    const float* z     = (const float*)d_in[0];   // [4096, 512]
    const float* W     = (const float*)d_in[1];   // [512, 512]
    const float* ldiag = (const float*)d_in[2];   // [10, 512]
    const int*   edges = (const int*)d_in[3];     // [2, n_edges] int32
    const int*   idxp  = (const int*)d_in[4];     // scalar

    const int n_drugs = in_sizes[0] / D;
    const int n_edges = in_sizes[3] / 2;

    static int smem_set = 0;
    if (!smem_set) {
        cudaFuncSetAttribute(dedicom_mma_kernel,
                             cudaFuncAttributeMaxDynamicSharedMemorySize, SM_GEMM);
        smem_set = 1;
    }

    prep_kernel<<<PREP_A_BLOCKS + PREP_W_BLOCKS, 256>>>(z, W, ldiag, idxp);

    dim3 gm(D / BN, n_drugs / BM);
    dedicom_mma_kernel<<<gm, 256, SM_GEMM>>>();

    int blocks = (n_edges + 7) / 8;
    dedicom_edge_kernel<<<blocks, 256>>>(edges, (float*)d_out, n_edges);
}